// round 3
// baseline (speedup 1.0000x reference)
#include <cuda_runtime.h>
#include <cuda_bf16.h>
#include <math.h>

#define Nn 100000
#define Ee 800000
#define Dd 64
#define HC 128
#define SCB 512
#define NSCAN_BLOCKS ((Nn + SCB - 1) / SCB)   // 196

// ---------------- device scratch (static: no allocation allowed) -------------
__device__ int   g_is64;
__device__ int   g_deg[Nn];
__device__ int   g_rowptr[Nn];
__device__ int   g_cursor[Nn];
__device__ int   g_colsrc[Ee];
__device__ int   g_bsums[NSCAN_BLOCKS + 8];
__device__ float g_xl[Nn * HC];   // 51.2 MB
__device__ float g_xr[Nn * HC];   // 51.2 MB
__device__ float g_x [Nn * Dd];   // 25.6 MB (inter-layer activations)

// ---------------- edge dtype detection (int64 vs int32) ----------------------
__global__ void k_detect(const void* edges) {
    if (threadIdx.x == 0) {
        const int* p = (const int*)edges;
        int all0 = 1;
        #pragma unroll 1
        for (int i = 1; i < 128; i += 2) {
            if (p[i] != 0) { all0 = 0; break; }
        }
        g_is64 = all0;   // node ids < 2^31 -> high words all zero iff int64
    }
}

__device__ __forceinline__ int edge_at(const void* edges, int i) {
    if (g_is64) return (int)((const long long*)edges)[i];
    return ((const int*)edges)[i];
}

// ---------------- CSR build --------------------------------------------------
__global__ void k_zero_deg() {
    int i = blockIdx.x * blockDim.x + threadIdx.x;
    if (i < Nn) g_deg[i] = 0;
}

__global__ void k_count(const void* edges) {
    int i = blockIdx.x * blockDim.x + threadIdx.x;
    if (i >= Ee) return;
    int dst = edge_at(edges, Ee + i);
    atomicAdd(&g_deg[dst], 1);
}

__global__ void k_scan1() {
    __shared__ int sh[SCB];
    int i = blockIdx.x * SCB + threadIdx.x;
    sh[threadIdx.x] = (i < Nn) ? g_deg[i] : 0;
    __syncthreads();
    for (int s = SCB / 2; s > 0; s >>= 1) {
        if (threadIdx.x < s) sh[threadIdx.x] += sh[threadIdx.x + s];
        __syncthreads();
    }
    if (threadIdx.x == 0) g_bsums[blockIdx.x] = sh[0];
}

__global__ void k_scan2(int nb) {
    if (threadIdx.x == 0) {
        int acc = 0;
        for (int b = 0; b < nb; b++) { int v = g_bsums[b]; g_bsums[b] = acc; acc += v; }
    }
}

__global__ void k_scan3() {
    __shared__ int sh[SCB];
    int i = blockIdx.x * SCB + threadIdx.x;
    int v = (i < Nn) ? g_deg[i] : 0;
    sh[threadIdx.x] = v;
    __syncthreads();
    for (int s = 1; s < SCB; s <<= 1) {
        int t = (threadIdx.x >= s) ? sh[threadIdx.x - s] : 0;
        __syncthreads();
        sh[threadIdx.x] += t;
        __syncthreads();
    }
    if (i < Nn) {
        int excl = g_bsums[blockIdx.x] + sh[threadIdx.x] - v;  // exclusive prefix
        g_rowptr[i] = excl;
        g_cursor[i] = excl;
    }
}

__global__ void k_scatter(const void* edges) {
    int i = blockIdx.x * blockDim.x + threadIdx.x;
    if (i >= Ee) return;
    int src = edge_at(edges, i);
    int dst = edge_at(edges, Ee + i);
    int pos = atomicAdd(&g_cursor[dst], 1);
    g_colsrc[pos] = src;
}

// ---------------- GEMM via bf16 split-precision tensor-core MMA --------------
// out[N,128] = x[N,64] @ W[64,128] + b,  computed as
//   hi(x)*hi(W) + lo(x)*hi(W) + hi(x)*lo(W)   (bf16x3, ~16 mantissa bits)
// blockIdx.y == 0 -> Wl/bl -> g_xl ; == 1 -> Wr/br -> g_xr
// Block: 128 rows x 128 cols, 256 threads = 8 warps (2x4), warp tile 64x32.
#define KP 72   // padded K stride in halfs (144 B = 36 banks -> conflict-free frags)

__device__ __forceinline__ void mma_bf16(float c[4], unsigned a0, unsigned a1,
                                         unsigned a2, unsigned a3,
                                         unsigned b0, unsigned b1) {
    asm volatile(
        "mma.sync.aligned.m16n8k16.row.col.f32.bf16.bf16.f32 "
        "{%0,%1,%2,%3}, {%4,%5,%6,%7}, {%8,%9}, {%0,%1,%2,%3};\n"
        : "+f"(c[0]), "+f"(c[1]), "+f"(c[2]), "+f"(c[3])
        : "r"(a0), "r"(a1), "r"(a2), "r"(a3), "r"(b0), "r"(b1));
}

__device__ __forceinline__ void split_bf16(float v, __nv_bfloat16& hi, __nv_bfloat16& lo) {
    hi = __float2bfloat16(v);
    lo = __float2bfloat16(v - __bfloat162float(hi));
}

__global__ __launch_bounds__(256)
void k_gemm(const float* __restrict__ xext, int use_gx,
            const float* __restrict__ Wl, const float* __restrict__ Wr,
            const float* __restrict__ bl, const float* __restrict__ br) {
    extern __shared__ __nv_bfloat16 sm[];
    __nv_bfloat16* Xhi = sm;                    // [128][KP]
    __nv_bfloat16* Xlo = sm + 128 * KP;
    __nv_bfloat16* Bhi = sm + 2 * 128 * KP;     // Wt [128 cols][KP k]
    __nv_bfloat16* Blo = sm + 3 * 128 * KP;

    const float* x = use_gx ? g_x : xext;
    const float* W = (blockIdx.y == 0) ? Wl : Wr;
    const float* bvec = (blockIdx.y == 0) ? bl : br;
    float* out = (blockIdx.y == 0) ? g_xl : g_xr;

    const int tid = threadIdx.x;
    const int row0 = blockIdx.x * 128;

    // load + split x tile [128][64]
    for (int i = tid; i < 128 * 16; i += 256) {
        int r = i >> 4, k4 = (i & 15) * 4;
        int row = row0 + r;
        float4 v = make_float4(0.f, 0.f, 0.f, 0.f);
        if (row < Nn) v = *(const float4*)(x + (size_t)row * 64 + k4);
        __nv_bfloat16 h, l;
        split_bf16(v.x, h, l); Xhi[r * KP + k4 + 0] = h; Xlo[r * KP + k4 + 0] = l;
        split_bf16(v.y, h, l); Xhi[r * KP + k4 + 1] = h; Xlo[r * KP + k4 + 1] = l;
        split_bf16(v.z, h, l); Xhi[r * KP + k4 + 2] = h; Xlo[r * KP + k4 + 2] = l;
        split_bf16(v.w, h, l); Xhi[r * KP + k4 + 3] = h; Xlo[r * KP + k4 + 3] = l;
    }
    // load + split + transpose W: Wt[c][k] = W[k][c]
    for (int i = tid; i < 64 * 128; i += 256) {
        int k = i >> 7, c = i & 127;
        __nv_bfloat16 h, l;
        split_bf16(W[i], h, l);
        Bhi[c * KP + k] = h;
        Blo[c * KP + k] = l;
    }
    __syncthreads();

    const int w = tid >> 5, lane = tid & 31;
    const int wr = (w >> 2) * 64;        // warp row base (0 / 64)
    const int wc = (w & 3) * 32;         // warp col base (0/32/64/96)
    const int grp = lane >> 2;           // 0..7
    const int q2 = (lane & 3) * 2;       // 0,2,4,6

    float acc[4][4][4];
    #pragma unroll
    for (int mt = 0; mt < 4; mt++)
        #pragma unroll
        for (int nt = 0; nt < 4; nt++)
            #pragma unroll
            for (int j = 0; j < 4; j++) acc[mt][nt][j] = 0.f;

    #pragma unroll
    for (int ks = 0; ks < 4; ks++) {
        const int k0 = ks * 16;
        unsigned ah[4][4], al[4][4], bh[4][2], bl2[4][2];
        #pragma unroll
        for (int mt = 0; mt < 4; mt++) {
            int r = wr + mt * 16 + grp;
            ah[mt][0] = *(const unsigned*)(&Xhi[(r    ) * KP + k0 + q2    ]);
            ah[mt][1] = *(const unsigned*)(&Xhi[(r + 8) * KP + k0 + q2    ]);
            ah[mt][2] = *(const unsigned*)(&Xhi[(r    ) * KP + k0 + q2 + 8]);
            ah[mt][3] = *(const unsigned*)(&Xhi[(r + 8) * KP + k0 + q2 + 8]);
            al[mt][0] = *(const unsigned*)(&Xlo[(r    ) * KP + k0 + q2    ]);
            al[mt][1] = *(const unsigned*)(&Xlo[(r + 8) * KP + k0 + q2    ]);
            al[mt][2] = *(const unsigned*)(&Xlo[(r    ) * KP + k0 + q2 + 8]);
            al[mt][3] = *(const unsigned*)(&Xlo[(r + 8) * KP + k0 + q2 + 8]);
        }
        #pragma unroll
        for (int nt = 0; nt < 4; nt++) {
            int n = wc + nt * 8 + grp;
            bh[nt][0]  = *(const unsigned*)(&Bhi[n * KP + k0 + q2    ]);
            bh[nt][1]  = *(const unsigned*)(&Bhi[n * KP + k0 + q2 + 8]);
            bl2[nt][0] = *(const unsigned*)(&Blo[n * KP + k0 + q2    ]);
            bl2[nt][1] = *(const unsigned*)(&Blo[n * KP + k0 + q2 + 8]);
        }
        #pragma unroll
        for (int mt = 0; mt < 4; mt++)
            #pragma unroll
            for (int nt = 0; nt < 4; nt++) {
                mma_bf16(acc[mt][nt], ah[mt][0], ah[mt][1], ah[mt][2], ah[mt][3],
                         bh[nt][0], bh[nt][1]);
                mma_bf16(acc[mt][nt], al[mt][0], al[mt][1], al[mt][2], al[mt][3],
                         bh[nt][0], bh[nt][1]);
                mma_bf16(acc[mt][nt], ah[mt][0], ah[mt][1], ah[mt][2], ah[mt][3],
                         bl2[nt][0], bl2[nt][1]);
            }
    }

    // epilogue: C frag (mt,nt): c0,c1 at (grp, q2/q2+1), c2,c3 at (grp+8, ...)
    #pragma unroll
    for (int mt = 0; mt < 4; mt++) {
        int r0g = row0 + wr + mt * 16 + grp;
        #pragma unroll
        for (int nt = 0; nt < 4; nt++) {
            int col = wc + nt * 8 + q2;
            float b0 = bvec[col], b1 = bvec[col + 1];
            if (r0g < Nn) {
                float2 o = make_float2(acc[mt][nt][0] + b0, acc[mt][nt][1] + b1);
                *(float2*)(out + (size_t)r0g * 128 + col) = o;
            }
            if (r0g + 8 < Nn) {
                float2 o = make_float2(acc[mt][nt][2] + b0, acc[mt][nt][3] + b1);
                *(float2*)(out + (size_t)(r0g + 8) * 128 + col) = o;
            }
        }
    }
}

// ---------------- fused attention: online softmax per dst node ---------------
__device__ __forceinline__ float gelu_tanh(float v) {
    float v3 = v * v * v;
    float t = tanhf(0.7978845608028654f * (v + 0.044715f * v3));
    return 0.5f * v * (1.f + t);
}

__global__ __launch_bounds__(256)
void k_attn(const float* __restrict__ att, const float* __restrict__ bias,
            float* __restrict__ dout, int layer) {
    int warp = (blockIdx.x * blockDim.x + threadIdx.x) >> 5;
    int lane = threadIdx.x & 31;
    if (warp >= Nn) return;
    const int n = warp;
    const int c4 = lane * 4;
    const unsigned full = 0xffffffffu;

    float4 xrv = *(const float4*)(g_xr + (size_t)n * HC + c4);
    float4 atv = *(const float4*)(att + c4);

    float m = -INFINITY, s = 0.f;
    float a0 = 0.f, a1 = 0.f, a2 = 0.f, a3 = 0.f;

    int start = g_rowptr[n];
    int cnt = g_deg[n];

    // software-pipelined loop: iteration 0 is the self loop (src = n)
    float4 xsv = *(const float4*)(g_xl + (size_t)n * HC + c4);
    for (int e = 0; e <= cnt; e++) {
        float4 cur = xsv;
        if (e < cnt) {
            int nsrc = g_colsrc[start + e];
            xsv = *(const float4*)(g_xl + (size_t)nsrc * HC + c4);
        }
        float z0 = cur.x + xrv.x, z1 = cur.y + xrv.y;
        float z2 = cur.z + xrv.z, z3 = cur.w + xrv.w;
        float l0 = (z0 > 0.f) ? z0 : 0.2f * z0;
        float l1 = (z1 > 0.f) ? z1 : 0.2f * z1;
        float l2 = (z2 > 0.f) ? z2 : 0.2f * z2;
        float l3 = (z3 > 0.f) ? z3 : 0.2f * z3;
        float p = l0 * atv.x + l1 * atv.y + l2 * atv.z + l3 * atv.w;
        // reduce within 16-lane half (head-local)
        p += __shfl_xor_sync(full, p, 1);
        p += __shfl_xor_sync(full, p, 2);
        p += __shfl_xor_sync(full, p, 4);
        p += __shfl_xor_sync(full, p, 8);
        // online softmax update
        float mn = fmaxf(m, p);
        float scale = expf(m - mn);      // expf(-inf)=0 handles first iter
        float coef  = expf(p - mn);
        s  = s * scale + coef;
        a0 = a0 * scale + coef * cur.x;
        a1 = a1 * scale + coef * cur.y;
        a2 = a2 * scale + coef * cur.z;
        a3 = a3 * scale + coef * cur.w;
        m = mn;
    }

    float inv = 1.f / (s + 1e-16f);
    float r0 = a0 * inv, r1 = a1 * inv, r2 = a2 * inv, r3 = a3 * inv;
    // combine heads: lane l (<16) pairs with lane l+16 (same channel, other head)
    float o0 = r0 + __shfl_xor_sync(full, r0, 16);
    float o1 = r1 + __shfl_xor_sync(full, r1, 16);
    float o2 = r2 + __shfl_xor_sync(full, r2, 16);
    float o3 = r3 + __shfl_xor_sync(full, r3, 16);

    if (lane < 16) {
        float4 bv = *(const float4*)(bias + c4);
        float y0 = 0.5f * o0 + bv.x;
        float y1 = 0.5f * o1 + bv.y;
        float y2 = 0.5f * o2 + bv.z;
        float y3 = 0.5f * o3 + bv.w;
        if (layer == 0) {
            y0 = gelu_tanh(y0); y1 = gelu_tanh(y1);
            y2 = gelu_tanh(y2); y3 = gelu_tanh(y3);
            *(float4*)(g_x + (size_t)n * Dd + c4) = make_float4(y0, y1, y2, y3);
        } else {
            *(float4*)(dout + (size_t)n * Dd + c4) = make_float4(y0, y1, y2, y3);
        }
    }
}

// ---------------- launcher ---------------------------------------------------
extern "C" void kernel_launch(void* const* d_in, const int* in_sizes, int n_in,
                              void* d_out, int out_size) {
    const float* x     = (const float*)d_in[0];
    const void*  edges = d_in[1];
    const float* Wl    = (const float*)d_in[2];
    const float* bl    = (const float*)d_in[3];
    const float* Wr    = (const float*)d_in[4];
    const float* br    = (const float*)d_in[5];
    const float* att   = (const float*)d_in[6];
    const float* bias  = (const float*)d_in[7];
    float* out = (float*)d_out;

    static int smem_set = 0;
    int gemm_smem = 4 * 128 * KP * (int)sizeof(__nv_bfloat16);  // 73728 B
    if (!smem_set) {
        cudaFuncSetAttribute(k_gemm, cudaFuncAttributeMaxDynamicSharedMemorySize, gemm_smem);
        smem_set = 1;
    }

    // CSR build (per call; graph-capturable, kernels only)
    k_detect  <<<1, 32>>>(edges);
    k_zero_deg<<<(Nn + 511) / 512, 512>>>();
    k_count   <<<(Ee + 255) / 256, 256>>>(edges);
    k_scan1   <<<NSCAN_BLOCKS, SCB>>>();
    k_scan2   <<<1, 32>>>(NSCAN_BLOCKS);
    k_scan3   <<<NSCAN_BLOCKS, SCB>>>();
    k_scatter <<<(Ee + 255) / 256, 256>>>(edges);

    dim3 ggrid((Nn + 127) / 128, 2);
    int agrid = (Nn + 7) / 8;   // one warp per node, 8 warps/block

    // layer 0
    k_gemm<<<ggrid, 256, gemm_smem>>>(x, 0, Wl, Wr, bl, br);
    k_attn<<<agrid, 256>>>(att, bias, out, 0);
    // layer 1
    k_gemm<<<ggrid, 256, gemm_smem>>>(x, 1, Wl + 64 * 128, Wr + 64 * 128,
                                      bl + 128, br + 128);
    k_attn<<<agrid, 256>>>(att + 128, bias + 64, out, 1);
}

// round 5
// speedup vs baseline: 1.3252x; 1.3252x over previous
#include <cuda_runtime.h>
#include <math.h>

#define Nn 100000
#define Ee 800000
#define Dd 64
#define HC 128
#define SCB 512
#define NSCAN_BLOCKS ((Nn + SCB - 1) / SCB)   // 196

// ---------------- device scratch (static: no allocation allowed) -------------
__device__ int   g_is64;
__device__ int   g_deg[Nn];
__device__ int   g_rowptr[Nn];
__device__ int   g_cursor[Nn];
__device__ int   g_colsrc[Ee];
__device__ int   g_bsums[NSCAN_BLOCKS + 8];
__device__ float g_xl[Nn * HC];   // 51.2 MB
__device__ float g_xr[Nn * HC];   // 51.2 MB
__device__ float g_x [Nn * Dd];   // 25.6 MB (inter-layer activations)

// ---------------- edge dtype detection (int64 vs int32) ----------------------
__global__ void k_detect(const void* edges) {
    if (threadIdx.x == 0) {
        const int* p = (const int*)edges;
        int all0 = 1;
        #pragma unroll 1
        for (int i = 1; i < 128; i += 2) {
            if (p[i] != 0) { all0 = 0; break; }
        }
        g_is64 = all0;   // node ids < 2^31 -> high words all zero iff int64
    }
}

__device__ __forceinline__ int edge_at(const void* edges, int i) {
    if (g_is64) return (int)((const long long*)edges)[i];
    return ((const int*)edges)[i];
}

// ---------------- CSR build --------------------------------------------------
__global__ void k_zero_deg() {
    int i = blockIdx.x * blockDim.x + threadIdx.x;
    if (i < Nn) g_deg[i] = 0;
}

__global__ void k_count(const void* edges) {
    int i = blockIdx.x * blockDim.x + threadIdx.x;
    if (i >= Ee) return;
    int dst = edge_at(edges, Ee + i);
    atomicAdd(&g_deg[dst], 1);
}

__global__ void k_scan1() {
    __shared__ int sh[SCB];
    int i = blockIdx.x * SCB + threadIdx.x;
    sh[threadIdx.x] = (i < Nn) ? g_deg[i] : 0;
    __syncthreads();
    for (int s = SCB / 2; s > 0; s >>= 1) {
        if (threadIdx.x < s) sh[threadIdx.x] += sh[threadIdx.x + s];
        __syncthreads();
    }
    if (threadIdx.x == 0) g_bsums[blockIdx.x] = sh[0];
}

__global__ void k_scan2(int nb) {
    if (threadIdx.x == 0) {
        int acc = 0;
        for (int b = 0; b < nb; b++) { int v = g_bsums[b]; g_bsums[b] = acc; acc += v; }
    }
}

__global__ void k_scan3() {
    __shared__ int sh[SCB];
    int i = blockIdx.x * SCB + threadIdx.x;
    int v = (i < Nn) ? g_deg[i] : 0;
    sh[threadIdx.x] = v;
    __syncthreads();
    for (int s = 1; s < SCB; s <<= 1) {
        int t = (threadIdx.x >= s) ? sh[threadIdx.x - s] : 0;
        __syncthreads();
        sh[threadIdx.x] += t;
        __syncthreads();
    }
    if (i < Nn) {
        int excl = g_bsums[blockIdx.x] + sh[threadIdx.x] - v;  // exclusive prefix
        g_rowptr[i] = excl;
        g_cursor[i] = excl;
    }
}

__global__ void k_scatter(const void* edges) {
    int i = blockIdx.x * blockDim.x + threadIdx.x;
    if (i >= Ee) return;
    int src = edge_at(edges, i);
    int dst = edge_at(edges, Ee + i);
    int pos = atomicAdd(&g_cursor[dst], 1);
    g_colsrc[pos] = src;
}

// ---------------- GEMM: out[N,128] = x[N,64] @ W[64,128] + b -----------------
// Packed-fp32 (fma.rn.f32x2 -> SASS FFMA2): 2 FMAs per fma-pipe slot.
// blockIdx.y == 0 -> Wl/bl -> g_xl ; == 1 -> Wr/br -> g_xr
// Tile: 128 rows x 128 cols, 256 threads, 8x8 per thread, K=64 resident.
#define AP 132   // padded row length for transposed A tile

typedef unsigned long long u64;

__device__ __forceinline__ u64 packf2(float a, float b) {
    u64 d;
    asm("mov.b64 %0, {%1, %2};" : "=l"(d) : "f"(a), "f"(b));
    return d;
}
__device__ __forceinline__ void unpackf2(u64 v, float& lo, float& hi) {
    asm("mov.b64 {%0, %1}, %2;" : "=f"(lo), "=f"(hi) : "l"(v));
}
__device__ __forceinline__ void fma2(u64& acc, u64 a, u64 b) {
    asm("fma.rn.f32x2 %0, %1, %2, %0;" : "+l"(acc) : "l"(a), "l"(b));
}

__global__ __launch_bounds__(256, 2)
void k_gemm(const float* __restrict__ xext, int use_gx,
            const float* __restrict__ Wl, const float* __restrict__ Wr,
            const float* __restrict__ bl, const float* __restrict__ br) {
    extern __shared__ float smem[];
    float* As = smem;              // [64][AP]  (transposed: As[k][r])
    float* Bs = smem + 64 * AP;    // [64][128]

    const float* x = use_gx ? g_x : xext;
    const float* W = (blockIdx.y == 0) ? Wl : Wr;
    const float* bvec = (blockIdx.y == 0) ? bl : br;
    float* out = (blockIdx.y == 0) ? g_xl : g_xr;

    int tid = threadIdx.x;
    int row0 = blockIdx.x * 128;

    // load W tile [64][128]
    for (int i = tid; i < 64 * 32; i += 256) {
        int k = i >> 5, c4 = (i & 31) * 4;
        float4 v = *(const float4*)(W + k * 128 + c4);
        *(float4*)(&Bs[k * 128 + c4]) = v;
    }
    // load x tile transposed: As[k][r] = x[row0+r][k]
    for (int i = tid; i < 128 * 16; i += 256) {
        int r = i >> 4, k4 = (i & 15) * 4;
        int row = row0 + r;
        float4 v = make_float4(0.f, 0.f, 0.f, 0.f);
        if (row < Nn) v = *(const float4*)(x + (size_t)row * 64 + k4);
        As[(k4 + 0) * AP + r] = v.x;
        As[(k4 + 1) * AP + r] = v.y;
        As[(k4 + 2) * AP + r] = v.z;
        As[(k4 + 3) * AP + r] = v.w;
    }
    __syncthreads();

    int tx = tid & 15, ty = tid >> 4;
    int ra = ty * 4, rb = 64 + ty * 4;
    int ca = tx * 4, cb = 64 + tx * 4;

    // acc[i][j]: row i (8 rows), col-pair j: j=0,1 -> cols ca..ca+3 ; j=2,3 -> cb..cb+3
    u64 acc[8][4];
    #pragma unroll
    for (int i = 0; i < 8; i++)
        #pragma unroll
        for (int j = 0; j < 4; j++) acc[i][j] = 0ull;

    #pragma unroll 4
    for (int k = 0; k < 64; k++) {
        float a[8];
        *(float4*)(a)     = *(float4*)(&As[k * AP + ra]);
        *(float4*)(a + 4) = *(float4*)(&As[k * AP + rb]);
        // b as packed col-pairs, straight from smem (adjacent cols)
        u64 b2[4];
        float4 bva = *(float4*)(&Bs[k * 128 + ca]);
        float4 bvb = *(float4*)(&Bs[k * 128 + cb]);
        b2[0] = packf2(bva.x, bva.y);
        b2[1] = packf2(bva.z, bva.w);
        b2[2] = packf2(bvb.x, bvb.y);
        b2[3] = packf2(bvb.z, bvb.w);
        u64 pa[8];
        #pragma unroll
        for (int i = 0; i < 8; i++) pa[i] = packf2(a[i], a[i]);
        #pragma unroll
        for (int i = 0; i < 8; i++) {
            fma2(acc[i][0], pa[i], b2[0]);
            fma2(acc[i][1], pa[i], b2[1]);
            fma2(acc[i][2], pa[i], b2[2]);
            fma2(acc[i][3], pa[i], b2[3]);
        }
    }

    float bb[8];
    *(float4*)(bb)     = *(const float4*)(bvec + ca);
    *(float4*)(bb + 4) = *(const float4*)(bvec + cb);

    #pragma unroll
    for (int i = 0; i < 8; i++) {
        int rl = (i < 4) ? (ra + i) : (rb + i - 4);
        int row = row0 + rl;
        if (row >= Nn) continue;
        float c0, c1, c2, c3, c4x, c5, c6, c7;
        unpackf2(acc[i][0], c0, c1);
        unpackf2(acc[i][1], c2, c3);
        unpackf2(acc[i][2], c4x, c5);
        unpackf2(acc[i][3], c6, c7);
        float4 o1 = make_float4(c0 + bb[0], c1 + bb[1], c2 + bb[2], c3 + bb[3]);
        float4 o2 = make_float4(c4x + bb[4], c5 + bb[5], c6 + bb[6], c7 + bb[7]);
        *(float4*)(out + (size_t)row * 128 + ca) = o1;
        *(float4*)(out + (size_t)row * 128 + cb) = o2;
    }
}

// ---------------- fused attention: online softmax per dst node ---------------
__device__ __forceinline__ float gelu_tanh(float v) {
    float v3 = v * v * v;
    float t = tanhf(0.7978845608028654f * (v + 0.044715f * v3));
    return 0.5f * v * (1.f + t);
}

__global__ __launch_bounds__(256)
void k_attn(const float* __restrict__ att, const float* __restrict__ bias,
            float* __restrict__ dout, int layer) {
    int warp = (blockIdx.x * blockDim.x + threadIdx.x) >> 5;
    int lane = threadIdx.x & 31;
    if (warp >= Nn) return;
    const int n = warp;
    const int c4 = lane * 4;
    const unsigned full = 0xffffffffu;

    float4 xrv = *(const float4*)(g_xr + (size_t)n * HC + c4);
    float4 atv = *(const float4*)(att + c4);

    float m = -INFINITY, s = 0.f;
    float a0 = 0.f, a1 = 0.f, a2 = 0.f, a3 = 0.f;

    int start = g_rowptr[n];
    int cnt = g_deg[n];

    // software-pipelined loop: iteration 0 is the self loop (src = n)
    float4 xsv = *(const float4*)(g_xl + (size_t)n * HC + c4);
    for (int e = 0; e <= cnt; e++) {
        float4 cur = xsv;
        if (e < cnt) {
            int nsrc = g_colsrc[start + e];
            xsv = *(const float4*)(g_xl + (size_t)nsrc * HC + c4);
        }
        float z0 = cur.x + xrv.x, z1 = cur.y + xrv.y;
        float z2 = cur.z + xrv.z, z3 = cur.w + xrv.w;
        float l0 = (z0 > 0.f) ? z0 : 0.2f * z0;
        float l1 = (z1 > 0.f) ? z1 : 0.2f * z1;
        float l2 = (z2 > 0.f) ? z2 : 0.2f * z2;
        float l3 = (z3 > 0.f) ? z3 : 0.2f * z3;
        float p = l0 * atv.x + l1 * atv.y + l2 * atv.z + l3 * atv.w;
        // reduce within 16-lane half (head-local)
        p += __shfl_xor_sync(full, p, 1);
        p += __shfl_xor_sync(full, p, 2);
        p += __shfl_xor_sync(full, p, 4);
        p += __shfl_xor_sync(full, p, 8);
        // online softmax update
        float mn = fmaxf(m, p);
        float scale = expf(m - mn);      // expf(-inf)=0 handles first iter
        float coef  = expf(p - mn);
        s  = s * scale + coef;
        a0 = a0 * scale + coef * cur.x;
        a1 = a1 * scale + coef * cur.y;
        a2 = a2 * scale + coef * cur.z;
        a3 = a3 * scale + coef * cur.w;
        m = mn;
    }

    float inv = 1.f / (s + 1e-16f);
    float r0 = a0 * inv, r1 = a1 * inv, r2 = a2 * inv, r3 = a3 * inv;
    // combine heads: lane l (<16) pairs with lane l+16 (same channel, other head)
    float o0 = r0 + __shfl_xor_sync(full, r0, 16);
    float o1 = r1 + __shfl_xor_sync(full, r1, 16);
    float o2 = r2 + __shfl_xor_sync(full, r2, 16);
    float o3 = r3 + __shfl_xor_sync(full, r3, 16);

    if (lane < 16) {
        float4 bv = *(const float4*)(bias + c4);
        float y0 = 0.5f * o0 + bv.x;
        float y1 = 0.5f * o1 + bv.y;
        float y2 = 0.5f * o2 + bv.z;
        float y3 = 0.5f * o3 + bv.w;
        if (layer == 0) {
            y0 = gelu_tanh(y0); y1 = gelu_tanh(y1);
            y2 = gelu_tanh(y2); y3 = gelu_tanh(y3);
            *(float4*)(g_x + (size_t)n * Dd + c4) = make_float4(y0, y1, y2, y3);
        } else {
            *(float4*)(dout + (size_t)n * Dd + c4) = make_float4(y0, y1, y2, y3);
        }
    }
}

// ---------------- launcher ---------------------------------------------------
extern "C" void kernel_launch(void* const* d_in, const int* in_sizes, int n_in,
                              void* d_out, int out_size) {
    const float* x     = (const float*)d_in[0];
    const void*  edges = d_in[1];
    const float* Wl    = (const float*)d_in[2];
    const float* bl    = (const float*)d_in[3];
    const float* Wr    = (const float*)d_in[4];
    const float* br    = (const float*)d_in[5];
    const float* att   = (const float*)d_in[6];
    const float* bias  = (const float*)d_in[7];
    float* out = (float*)d_out;

    static int smem_set = 0;
    int gemm_smem = (64 * AP + 64 * 128) * (int)sizeof(float);  // 66560 B
    if (!smem_set) {
        cudaFuncSetAttribute(k_gemm, cudaFuncAttributeMaxDynamicSharedMemorySize, gemm_smem);
        smem_set = 1;
    }

    // CSR build (per call; graph-capturable, kernels only)
    k_detect  <<<1, 32>>>(edges);
    k_zero_deg<<<(Nn + 511) / 512, 512>>>();
    k_count   <<<(Ee + 255) / 256, 256>>>(edges);
    k_scan1   <<<NSCAN_BLOCKS, SCB>>>();
    k_scan2   <<<1, 32>>>(NSCAN_BLOCKS);
    k_scan3   <<<NSCAN_BLOCKS, SCB>>>();
    k_scatter <<<(Ee + 255) / 256, 256>>>(edges);

    dim3 ggrid((Nn + 127) / 128, 2);
    int agrid = (Nn + 7) / 8;   // one warp per node, 8 warps/block

    // layer 0
    k_gemm<<<ggrid, 256, gemm_smem>>>(x, 0, Wl, Wr, bl, br);
    k_attn<<<agrid, 256>>>(att, bias, out, 0);
    // layer 1
    k_gemm<<<ggrid, 256, gemm_smem>>>(x, 1, Wl + 64 * 128, Wr + 64 * 128,
                                      bl + 128, br + 128);
    k_attn<<<agrid, 256>>>(att + 128, bias + 64, out, 1);
}